// round 13
// baseline (speedup 1.0000x reference)
#include <cuda_runtime.h>
#include <cuda_bf16.h>
#include <cuda_fp16.h>
#include <stdint.h>

#define NN 4096
#define FIN 512
#define FOUT 128
#define HEADS 4
#define COUT 512
#define ALPHA 0.2f
#define PSCALE 0.015625f   // 2^-6, cancels in normalization

// ---------------- scratch ----------------
__device__ __align__(128) float g_src[HEADS * NN];
__device__ __align__(128) float g_dst[HEADS * NN];
__device__ __align__(128) __half g_Ht[COUT * NN];               // [c][m] fp16
__device__ __align__(128) __nv_bfloat16 g_xhi[NN * FIN];        // [m][i]
__device__ __align__(128) __nv_bfloat16 g_xlo[NN * FIN];
__device__ __align__(128) __nv_bfloat16 g_Wthi[COUT * FIN];     // [c][i]
__device__ __align__(128) __nv_bfloat16 g_Wtlo[COUT * FIN];

// ---------------- helpers ----------------
__device__ __forceinline__ uint32_t smem_u32(const void* p) {
    uint32_t a;
    asm("{ .reg .u64 t; cvta.to.shared.u64 t, %1; cvt.u32.u64 %0, t; }" : "=r"(a) : "l"(p));
    return a;
}
#define SWZ(off)    ((off) ^ (((off) >> 3) & 0x70))   // 128B rows
#define SWZ256(off) ((off) ^ (((off) >> 4) & 0x70))   // 256B rows
#define CP_ASYNC16(dst, src) \
    asm volatile("cp.async.cg.shared.global [%0], [%1], 16;" :: "r"(dst), "l"(src) : "memory")
#define CP_COMMIT() asm volatile("cp.async.commit_group;" ::: "memory")
#define CP_WAIT0()  asm volatile("cp.async.wait_group 0;" ::: "memory")

__device__ __forceinline__ void ldsm4(uint32_t* r, uint32_t a) {
    asm volatile("ldmatrix.sync.aligned.m8n8.x4.shared.b16 {%0,%1,%2,%3}, [%4];"
                 : "=r"(r[0]), "=r"(r[1]), "=r"(r[2]), "=r"(r[3]) : "r"(a));
}
__device__ __forceinline__ void mma_bf16(float* d, const uint32_t* a, uint32_t b0, uint32_t b1) {
    asm volatile(
        "mma.sync.aligned.m16n8k16.row.col.f32.bf16.bf16.f32 "
        "{%0,%1,%2,%3},{%4,%5,%6,%7},{%8,%9},{%0,%1,%2,%3};"
        : "+f"(d[0]), "+f"(d[1]), "+f"(d[2]), "+f"(d[3])
        : "r"(a[0]), "r"(a[1]), "r"(a[2]), "r"(a[3]), "r"(b0), "r"(b1));
}
__device__ __forceinline__ void mma_f16(float* d, const uint32_t* a, uint32_t b0, uint32_t b1) {
    asm volatile(
        "mma.sync.aligned.m16n8k16.row.col.f32.f16.f16.f32 "
        "{%0,%1,%2,%3},{%4,%5,%6,%7},{%8,%9},{%0,%1,%2,%3};"
        : "+f"(d[0]), "+f"(d[1]), "+f"(d[2]), "+f"(d[3])
        : "r"(a[0]), "r"(a[1]), "r"(a[2]), "r"(a[3]), "r"(b0), "r"(b1));
}
__device__ __forceinline__ void split_bf16(float v, __nv_bfloat16& hi, __nv_bfloat16& lo) {
    hi = __float2bfloat16(v);
    lo = __float2bfloat16(v - __bfloat162float(hi));
}

// ---------------- Kernel I: init scores ----------------
__global__ __launch_bounds__(256) void k_init(const float* __restrict__ ab)
{
    const int idx = blockIdx.x * 256 + threadIdx.x;
    g_src[idx] = ab[idx >> 12];
    g_dst[idx] = 0.f;
}

// ---------------- Kernel A: split x into bf16 hi/lo ----------------
__global__ __launch_bounds__(256) void k_split_x(const float* __restrict__ x)
{
    const int base = (blockIdx.x * 256 + threadIdx.x) * 8;
    float4 v0 = *(const float4*)(x + base);
    float4 v1 = *(const float4*)(x + base + 4);
    float v[8] = {v0.x, v0.y, v0.z, v0.w, v1.x, v1.y, v1.z, v1.w};
    __align__(16) __nv_bfloat16 hb[8], lb[8];
#pragma unroll
    for (int j = 0; j < 8; j++) split_bf16(v[j], hb[j], lb[j]);
    *(uint4*)(g_xhi + base) = *(const uint4*)hb;
    *(uint4*)(g_xlo + base) = *(const uint4*)lb;
}

// ---------------- Kernel B: W[h][i][o] -> Wt[c][i] bf16 hi/lo ----------------
__global__ __launch_bounds__(256) void k_split_w(const float* __restrict__ W)
{
    __shared__ float tile[32][33];
    const int tx = threadIdx.x & 31, ty = threadIdx.x >> 5;
    const int i0 = blockIdx.x * 32, o0 = blockIdx.y * 32, h = blockIdx.z;
#pragma unroll
    for (int k = 0; k < 4; k++)
        tile[ty + 8 * k][tx] = W[((size_t)h * FIN + i0 + ty + 8 * k) * FOUT + o0 + tx];
    __syncthreads();
#pragma unroll
    for (int k = 0; k < 4; k++) {
        int o = o0 + ty + 8 * k;
        float v = tile[tx][ty + 8 * k];
        __nv_bfloat16 hi, lo;
        split_bf16(v, hi, lo);
        g_Wthi[(size_t)(h * FOUT + o) * FIN + i0 + tx] = hi;
        g_Wtlo[(size_t)(h * FOUT + o) * FIN + i0 + tx] = lo;
    }
}

// ---------------- Kernel 1: h = x @ Wc + b via HMMA (bf16 3-term) ----------------
// Fused epilogue: score partials (atomicAdd) + transpose + fp16 cvt of h.
#define GA_H(buf) ((buf) * 16384)
#define GA_L(buf) (32768 + (buf) * 16384)
#define GB_H(buf) (65536 + (buf) * 8192)
#define GB_L(buf) (81920 + (buf) * 8192)
#define GSMEM 98304

__global__ __launch_bounds__(256, 2) void k_gemm_h(
    const float* __restrict__ b, const float* __restrict__ aw)
{
    extern __shared__ char smem[];
    const uint32_t sb = smem_u32(smem);
    const int t = threadIdx.x;
    const int wid = t >> 5, l = t & 31;
    const int m0 = blockIdx.x * 128;
    const int c0 = blockIdx.y * 64;
    const int h = c0 >> 7;

    const int ar = t >> 1, ah_ = (t & 1);
    const int br = t >> 2, bq = (t & 3);
    const __nv_bfloat16* xh = g_xhi + (size_t)(m0 + ar) * FIN + ah_ * 32;
    const __nv_bfloat16* xl = g_xlo + (size_t)(m0 + ar) * FIN + ah_ * 32;
    const __nv_bfloat16* wh = g_Wthi + (size_t)(c0 + br) * FIN + bq * 16;
    const __nv_bfloat16* wl = g_Wtlo + (size_t)(c0 + br) * FIN + bq * 16;
    uint32_t aDst[4], bDst[2];
#pragma unroll
    for (int q = 0; q < 4; q++) aDst[q] = SWZ((uint32_t)(ar * 128 + ah_ * 64 + q * 16));
#pragma unroll
    for (int q = 0; q < 2; q++) bDst[q] = SWZ((uint32_t)(br * 128 + bq * 32 + q * 16));

    const int wr = wid & 3, wc = wid >> 2;
    uint32_t aOff[4], bOff[2][4];
    {
        uint32_t aBase = (uint32_t)((wr * 32 + (l & 15)) * 128 + ((l >> 4) << 4));
#pragma unroll
        for (int ks = 0; ks < 4; ks++) aOff[ks] = SWZ(aBase + ks * 32);
#pragma unroll
        for (int gg = 0; gg < 2; gg++) {
            uint32_t bBase = (uint32_t)((wc * 32 + gg * 16 + (l & 15)) * 128 + ((l >> 4) << 4));
#pragma unroll
            for (int ks = 0; ks < 4; ks++) bOff[gg][ks] = SWZ(bBase + ks * 32);
        }
    }

    float acc[2][4][4];
#pragma unroll
    for (int mt = 0; mt < 2; mt++)
#pragma unroll
        for (int nt = 0; nt < 4; nt++)
#pragma unroll
            for (int q = 0; q < 4; q++) acc[mt][nt][q] = 0.f;

    auto stage = [&](int chunk) {
        const int k0 = chunk * 64;
        const int buf = chunk & 1;
        const uint32_t pah = sb + GA_H(buf), pal = sb + GA_L(buf);
        const uint32_t pbh = sb + GB_H(buf), pbl = sb + GB_L(buf);
#pragma unroll
        for (int q = 0; q < 4; q++) CP_ASYNC16(pah + aDst[q], xh + k0 + q * 8);
#pragma unroll
        for (int q = 0; q < 4; q++) CP_ASYNC16(pal + aDst[q], xl + k0 + q * 8);
#pragma unroll
        for (int q = 0; q < 2; q++) CP_ASYNC16(pbh + bDst[q], wh + k0 + q * 8);
#pragma unroll
        for (int q = 0; q < 2; q++) CP_ASYNC16(pbl + bDst[q], wl + k0 + q * 8);
    };

    auto compute = [&](int buf) {
        const uint32_t tAh = sb + GA_H(buf), tAl = sb + GA_L(buf);
        const uint32_t tBh = sb + GB_H(buf), tBl = sb + GB_L(buf);
#pragma unroll
        for (int ks = 0; ks < 4; ks++) {
            uint32_t ah0[4], ah1[4], al0[4], al1[4];
            ldsm4(ah0, tAh + aOff[ks]);
            ldsm4(ah1, tAh + aOff[ks] + 2048);
            ldsm4(al0, tAl + aOff[ks]);
            ldsm4(al1, tAl + aOff[ks] + 2048);
#pragma unroll
            for (int gg = 0; gg < 2; gg++) {
                uint32_t bh[4], bl[4];
                ldsm4(bh, tBh + bOff[gg][ks]);
                ldsm4(bl, tBl + bOff[gg][ks]);
#pragma unroll
                for (int j = 0; j < 2; j++) {
                    int nt = gg * 2 + j;
                    mma_bf16(acc[0][nt], ah0, bh[j], bh[j + 2]);
                    mma_bf16(acc[0][nt], al0, bh[j], bh[j + 2]);
                    mma_bf16(acc[0][nt], ah0, bl[j], bl[j + 2]);
                    mma_bf16(acc[1][nt], ah1, bh[j], bh[j + 2]);
                    mma_bf16(acc[1][nt], al1, bh[j], bh[j + 2]);
                    mma_bf16(acc[1][nt], ah1, bl[j], bl[j + 2]);
                }
            }
        }
    };

    stage(0);
    CP_COMMIT();
    CP_WAIT0();
    __syncthreads();
    for (int chunk = 0; chunk < 8; chunk++) {
        if (chunk + 1 < 8) { stage(chunk + 1); CP_COMMIT(); }
        compute(chunk & 1);
        CP_WAIT0();
        __syncthreads();
    }

    // ==== fused epilogue ====
    const int rq = l >> 2, cq = (l & 3) * 2;

    float ps[2][2] = {{0.f, 0.f}, {0.f, 0.f}};
    float pd[2][2] = {{0.f, 0.f}, {0.f, 0.f}};
#pragma unroll
    for (int nt = 0; nt < 4; nt++) {
        int cg = c0 + wc * 32 + nt * 8 + cq;
        int o = cg & 127;
        float2 bias = *(const float2*)&b[cg];
        float as0 = aw[h * 256 + o], as1 = aw[h * 256 + o + 1];
        float ad0 = aw[h * 256 + 128 + o], ad1 = aw[h * 256 + 128 + o + 1];
#pragma unroll
        for (int mt = 0; mt < 2; mt++) {
            acc[mt][nt][0] += bias.x; acc[mt][nt][1] += bias.y;
            acc[mt][nt][2] += bias.x; acc[mt][nt][3] += bias.y;
            ps[mt][0] = fmaf(acc[mt][nt][0], as0, fmaf(acc[mt][nt][1], as1, ps[mt][0]));
            ps[mt][1] = fmaf(acc[mt][nt][2], as0, fmaf(acc[mt][nt][3], as1, ps[mt][1]));
            pd[mt][0] = fmaf(acc[mt][nt][0], ad0, fmaf(acc[mt][nt][1], ad1, pd[mt][0]));
            pd[mt][1] = fmaf(acc[mt][nt][2], ad0, fmaf(acc[mt][nt][3], ad1, pd[mt][1]));
        }
    }
#pragma unroll
    for (int off = 1; off <= 2; off <<= 1) {
#pragma unroll
        for (int mt = 0; mt < 2; mt++) {
            ps[mt][0] += __shfl_xor_sync(0xffffffffu, ps[mt][0], off);
            ps[mt][1] += __shfl_xor_sync(0xffffffffu, ps[mt][1], off);
            pd[mt][0] += __shfl_xor_sync(0xffffffffu, pd[mt][0], off);
            pd[mt][1] += __shfl_xor_sync(0xffffffffu, pd[mt][1], off);
        }
    }
    if ((l & 3) == 0) {
#pragma unroll
        for (int mt = 0; mt < 2; mt++) {
            int n = m0 + wr * 32 + mt * 16 + rq;
            atomicAdd(&g_src[h * NN + n], ps[mt][0]);
            atomicAdd(&g_src[h * NN + n + 8], ps[mt][1]);
            atomicAdd(&g_dst[h * NN + n], pd[mt][0]);
            atomicAdd(&g_dst[h * NN + n + 8], pd[mt][1]);
        }
    }

    // 2) transpose via smem + fp16 cvt + coalesced STG
    __syncthreads();
    float* tf = (float*)smem;
#pragma unroll
    for (int nt = 0; nt < 4; nt++) {
        int c = wc * 32 + nt * 8 + cq;
#pragma unroll
        for (int mt = 0; mt < 2; mt++) {
            int m = wr * 32 + mt * 16 + rq;
            tf[c * 132 + m] = acc[mt][nt][0];
            tf[(c + 1) * 132 + m] = acc[mt][nt][1];
            tf[c * 132 + m + 8] = acc[mt][nt][2];
            tf[(c + 1) * 132 + m + 8] = acc[mt][nt][3];
        }
    }
    __syncthreads();
    {
        const int c = t >> 2, seg = t & 3;
        const float* src = tf + c * 132 + seg * 32;
        __align__(16) __half hb[32];
#pragma unroll
        for (int k = 0; k < 32; k++) hb[k] = __float2half_rn(src[k]);
        __half* dhi = g_Ht + (size_t)(c0 + c) * NN + m0 + seg * 32;
#pragma unroll
        for (int q = 0; q < 4; q++)
            *(uint4*)(dhi + q * 8) = *(const uint4*)(hb + q * 8);
    }
}

// ---------------- Kernel 4: out = softmax(P) @ H, fp16, M=128 chunks ----------------
// smem: A[2]@0 (16KB ea, 64n x 128m fp16, 256B rows), B[2]@32K (32KB ea, 128c x 128m),
//       srow@96K. Total 96.5KB -> 2 CTA/SM.
#define SM_A(buf) ((buf) * 16384)
#define SM_B(buf) (32768 + (buf) * 32768)
#define SM_SROW 98304
#define SMEM_TOTAL (98304 + 512)

__global__ __launch_bounds__(256, 2) void k_attn_mma(const int* __restrict__ adj, float* __restrict__ out)
{
    extern __shared__ char smem[];
    const uint32_t sb = smem_u32(smem);
    const int t = threadIdx.x;
    const int wid = t >> 5, l = t & 31;
    const int h = blockIdx.x & 3;
    const int n0 = (blockIdx.x >> 2) * 64;

    // ---- staging roles ----
    const int np = t >> 2, mg = (t & 3) * 32;     // P: row np (0..63), 32 m's
    const int cr = t >> 1, mh = (t & 1) * 64;     // H: row cr (0..127), 64 m's
    const float sS = g_src[h * NN + n0 + np];
    const int* arow = adj + (size_t)(n0 + np) * NN + mg;
    const float* gdst = g_dst + h * NN + mg;
    const __half* ght = g_Ht + (size_t)(h * 128 + cr) * NN + mh;
    uint32_t hDst[8], pDst[4];
#pragma unroll
    for (int q = 0; q < 8; q++) hDst[q] = SWZ256((uint32_t)(cr * 256 + mh * 2 + q * 16));
#pragma unroll
    for (int q = 0; q < 4; q++) pDst[q] = SWZ256((uint32_t)(np * 256 + mg * 2 + q * 16));

    // ---- compute role: warp (wr 0..3, wc 0..1) owns 16n x 64c ----
    const int wr = wid & 3;
    const int wc = wid >> 2;
    uint32_t aOffk[8], bOffk[8];
    {
        uint32_t aBase = (uint32_t)((wr * 16 + (l & 15)) * 256 + ((l >> 4) << 4));
        uint32_t bBase = (uint32_t)((wc * 64 + (l & 15)) * 256 + ((l >> 4) << 4));
#pragma unroll
        for (int ks = 0; ks < 8; ks++) {
            aOffk[ks] = SWZ256(aBase + ks * 32);
            bOffk[ks] = SWZ256(bBase + ks * 32);
        }
    }

    float acc[8][4];
#pragma unroll
    for (int nt = 0; nt < 8; nt++)
#pragma unroll
        for (int q = 0; q < 4; q++) acc[nt][q] = 0.f;

    float psum = 0.f;

    auto stageH = [&](int chunk) {
        const int m0 = chunk * 128;
        const uint32_t bB = sb + SM_B(chunk & 1);
#pragma unroll
        for (int q = 0; q < 8; q++) CP_ASYNC16(bB + hDst[q], ght + m0 + q * 8);
    };

    auto stageP = [&](int chunk) {
        const int m0 = chunk * 128;
        char* Ah = smem + SM_A(chunk & 1);
#pragma unroll
        for (int half = 0; half < 2; half++) {
            const int mo = m0 + half * 16;
            int4 a0 = *(const int4*)(arow + mo);
            int4 a1 = *(const int4*)(arow + mo + 4);
            int4 a2 = *(const int4*)(arow + mo + 8);
            int4 a3 = *(const int4*)(arow + mo + 12);
            float4 d0 = *(const float4*)(gdst + mo);
            float4 d1 = *(const float4*)(gdst + mo + 4);
            float4 d2 = *(const float4*)(gdst + mo + 8);
            float4 d3 = *(const float4*)(gdst + mo + 12);
            int av[16] = {a0.x, a0.y, a0.z, a0.w, a1.x, a1.y, a1.z, a1.w,
                          a2.x, a2.y, a2.z, a2.w, a3.x, a3.y, a3.z, a3.w};
            float dv[16] = {d0.x, d0.y, d0.z, d0.w, d1.x, d1.y, d1.z, d1.w,
                            d2.x, d2.y, d2.z, d2.w, d3.x, d3.y, d3.z, d3.w};
            __align__(16) __half hb[16];
#pragma unroll
            for (int j = 0; j < 16; j++) {
                float xx = sS + dv[j];
                float e = xx > 0.f ? xx : ALPHA * xx;
                float p = (av[j] > 0) ? __expf(e) * PSCALE : 0.f;
                __half ph = __float2half_rn(p);
                hb[j] = ph;
                psum += __half2float(ph);
            }
            *(uint4*)(Ah + pDst[half * 2]) = *(const uint4*)hb;
            *(uint4*)(Ah + pDst[half * 2 + 1]) = *(const uint4*)(hb + 8);
        }
    };

    auto compute = [&](int buf) {
        const uint32_t tA = sb + SM_A(buf);
        const uint32_t tB = sb + SM_B(buf);
#pragma unroll
        for (int ks = 0; ks < 8; ks++) {
            uint32_t ap[4];
            ldsm4(ap, tA + aOffk[ks]);
#pragma unroll
            for (int gg = 0; gg < 4; gg++) {
                uint32_t bh[4];
                ldsm4(bh, tB + bOffk[ks] + gg * 4096);
#pragma unroll
                for (int j = 0; j < 2; j++)
                    mma_f16(acc[gg * 2 + j], ap, bh[j], bh[j + 2]);
            }
        }
    };

    // prologue
    stageH(0);
    CP_COMMIT();
    stageP(0);
    CP_WAIT0();
    __syncthreads();

    for (int chunk = 0; chunk < 32; chunk++) {
        if (chunk + 1 < 32) {
            stageH(chunk + 1);
            CP_COMMIT();
            stageP(chunk + 1);
        }
        compute(chunk & 1);
        CP_WAIT0();
        __syncthreads();
    }

    // ---- row-sum reduction: 4 threads per row ----
    psum += __shfl_xor_sync(0xffffffffu, psum, 1);
    psum += __shfl_xor_sync(0xffffffffu, psum, 2);
    float* srow = (float*)(smem + SM_SROW);
    if ((t & 3) == 0) srow[np] = psum;
    __syncthreads();

    // ---- epilogue: normalize + store (scale cancels exactly) ----
    const int rq = l >> 2, cq = (l & 3) * 2;
    const float inv0 = 1.0f / srow[wr * 16 + rq];
    const float inv1 = 1.0f / srow[wr * 16 + rq + 8];
#pragma unroll
    for (int nt = 0; nt < 8; nt++) {
        int n = n0 + wr * 16 + rq;
        int cg = h * FOUT + wc * 64 + nt * 8 + cq;
        float2 v0 = {acc[nt][0] * inv0, acc[nt][1] * inv0};
        float2 v1 = {acc[nt][2] * inv1, acc[nt][3] * inv1};
        *(float2*)&out[(size_t)n * COUT + cg] = v0;
        *(float2*)&out[(size_t)(n + 8) * COUT + cg] = v1;
    }
}

// ---------------- launch ----------------
extern "C" void kernel_launch(void* const* d_in, const int* in_sizes, int n_in,
                              void* d_out, int out_size)
{
    const float* x   = (const float*)d_in[0];
    const int*   adj = (const int*)d_in[1];
    const float* W   = (const float*)d_in[2];
    const float* b   = (const float*)d_in[3];
    const float* aw  = (const float*)d_in[4];
    const float* ab  = (const float*)d_in[5];
    float* out = (float*)d_out;

    (void)cudaFuncSetAttribute(k_gemm_h, cudaFuncAttributeMaxDynamicSharedMemorySize, GSMEM);
    (void)cudaFuncSetAttribute(k_attn_mma, cudaFuncAttributeMaxDynamicSharedMemorySize, SMEM_TOTAL);

    k_init<<<HEADS * NN / 256, 256>>>(ab);
    k_split_x<<<NN * FIN / (256 * 8), 256>>>(x);
    k_split_w<<<dim3(FIN / 32, FOUT / 32, HEADS), 256>>>(W);
    k_gemm_h<<<dim3(NN / 128, COUT / 64), 256, GSMEM>>>(b, aw);
    k_attn_mma<<<256, 256, SMEM_TOTAL>>>(adj, out);
}

// round 14
// speedup vs baseline: 1.2081x; 1.2081x over previous
#include <cuda_runtime.h>
#include <cuda_bf16.h>
#include <cuda_fp16.h>
#include <stdint.h>

#define NN 4096
#define FIN 512
#define FOUT 128
#define HEADS 4
#define COUT 512
#define ALPHA 0.2f
#define PSCALE 0.015625f   // 2^-6, cancels in normalization

// ---------------- scratch ----------------
__device__ __align__(128) float g_src[HEADS * NN];
__device__ __align__(128) float g_dst[HEADS * NN];
__device__ __align__(128) __half g_Ht[COUT * NN];               // [c][m] fp16
__device__ __align__(128) __nv_bfloat16 g_xhi[NN * FIN];        // [m][i]
__device__ __align__(128) __nv_bfloat16 g_xlo[NN * FIN];
__device__ __align__(128) __nv_bfloat16 g_Wthi[COUT * FIN];     // [c][i]
__device__ __align__(128) __nv_bfloat16 g_Wtlo[COUT * FIN];

// ---------------- helpers ----------------
__device__ __forceinline__ uint32_t smem_u32(const void* p) {
    uint32_t a;
    asm("{ .reg .u64 t; cvta.to.shared.u64 t, %1; cvt.u32.u64 %0, t; }" : "=r"(a) : "l"(p));
    return a;
}
#define SWZ(off) ((off) ^ (((off) >> 3) & 0x70))   // 128B rows
#define CP_ASYNC16(dst, src) \
    asm volatile("cp.async.cg.shared.global [%0], [%1], 16;" :: "r"(dst), "l"(src) : "memory")
#define CP_COMMIT() asm volatile("cp.async.commit_group;" ::: "memory")
#define CP_WAIT0()  asm volatile("cp.async.wait_group 0;" ::: "memory")

__device__ __forceinline__ void ldsm4(uint32_t* r, uint32_t a) {
    asm volatile("ldmatrix.sync.aligned.m8n8.x4.shared.b16 {%0,%1,%2,%3}, [%4];"
                 : "=r"(r[0]), "=r"(r[1]), "=r"(r[2]), "=r"(r[3]) : "r"(a));
}
__device__ __forceinline__ void mma_bf16(float* d, const uint32_t* a, uint32_t b0, uint32_t b1) {
    asm volatile(
        "mma.sync.aligned.m16n8k16.row.col.f32.bf16.bf16.f32 "
        "{%0,%1,%2,%3},{%4,%5,%6,%7},{%8,%9},{%0,%1,%2,%3};"
        : "+f"(d[0]), "+f"(d[1]), "+f"(d[2]), "+f"(d[3])
        : "r"(a[0]), "r"(a[1]), "r"(a[2]), "r"(a[3]), "r"(b0), "r"(b1));
}
__device__ __forceinline__ void mma_f16(float* d, const uint32_t* a, uint32_t b0, uint32_t b1) {
    asm volatile(
        "mma.sync.aligned.m16n8k16.row.col.f32.f16.f16.f32 "
        "{%0,%1,%2,%3},{%4,%5,%6,%7},{%8,%9},{%0,%1,%2,%3};"
        : "+f"(d[0]), "+f"(d[1]), "+f"(d[2]), "+f"(d[3])
        : "r"(a[0]), "r"(a[1]), "r"(a[2]), "r"(a[3]), "r"(b0), "r"(b1));
}
__device__ __forceinline__ void split_bf16(float v, __nv_bfloat16& hi, __nv_bfloat16& lo) {
    hi = __float2bfloat16(v);
    lo = __float2bfloat16(v - __bfloat162float(hi));
}

// ---------------- Kernel I: init scores ----------------
__global__ __launch_bounds__(256) void k_init(const float* __restrict__ ab)
{
    const int idx = blockIdx.x * 256 + threadIdx.x;
    g_src[idx] = ab[idx >> 12];
    g_dst[idx] = 0.f;
}

// ---------------- Kernel A: split x into bf16 hi/lo ----------------
__global__ __launch_bounds__(256) void k_split_x(const float* __restrict__ x)
{
    const int base = (blockIdx.x * 256 + threadIdx.x) * 8;
    float4 v0 = *(const float4*)(x + base);
    float4 v1 = *(const float4*)(x + base + 4);
    float v[8] = {v0.x, v0.y, v0.z, v0.w, v1.x, v1.y, v1.z, v1.w};
    __align__(16) __nv_bfloat16 hb[8], lb[8];
#pragma unroll
    for (int j = 0; j < 8; j++) split_bf16(v[j], hb[j], lb[j]);
    *(uint4*)(g_xhi + base) = *(const uint4*)hb;
    *(uint4*)(g_xlo + base) = *(const uint4*)lb;
}

// ---------------- Kernel B: W[h][i][o] -> Wt[c][i] bf16 hi/lo ----------------
__global__ __launch_bounds__(256) void k_split_w(const float* __restrict__ W)
{
    __shared__ float tile[32][33];
    const int tx = threadIdx.x & 31, ty = threadIdx.x >> 5;
    const int i0 = blockIdx.x * 32, o0 = blockIdx.y * 32, h = blockIdx.z;
#pragma unroll
    for (int k = 0; k < 4; k++)
        tile[ty + 8 * k][tx] = W[((size_t)h * FIN + i0 + ty + 8 * k) * FOUT + o0 + tx];
    __syncthreads();
#pragma unroll
    for (int k = 0; k < 4; k++) {
        int o = o0 + ty + 8 * k;
        float v = tile[tx][ty + 8 * k];
        __nv_bfloat16 hi, lo;
        split_bf16(v, hi, lo);
        g_Wthi[(size_t)(h * FOUT + o) * FIN + i0 + tx] = hi;
        g_Wtlo[(size_t)(h * FOUT + o) * FIN + i0 + tx] = lo;
    }
}

// ---------------- Kernel 1: h = x @ Wc + b via HMMA (bf16 3-term) ----------------
// Fused epilogue: score partials (atomicAdd) + transpose + fp16 cvt of h.
#define GA_H(buf) ((buf) * 16384)
#define GA_L(buf) (32768 + (buf) * 16384)
#define GB_H(buf) (65536 + (buf) * 8192)
#define GB_L(buf) (81920 + (buf) * 8192)
#define GSMEM 98304

__global__ __launch_bounds__(256, 2) void k_gemm_h(
    const float* __restrict__ b, const float* __restrict__ aw)
{
    extern __shared__ char smem[];
    const uint32_t sb = smem_u32(smem);
    const int t = threadIdx.x;
    const int wid = t >> 5, l = t & 31;
    const int m0 = blockIdx.x * 128;
    const int c0 = blockIdx.y * 64;
    const int h = c0 >> 7;

    const int ar = t >> 1, ah_ = (t & 1);
    const int br = t >> 2, bq = (t & 3);
    const __nv_bfloat16* xh = g_xhi + (size_t)(m0 + ar) * FIN + ah_ * 32;
    const __nv_bfloat16* xl = g_xlo + (size_t)(m0 + ar) * FIN + ah_ * 32;
    const __nv_bfloat16* wh = g_Wthi + (size_t)(c0 + br) * FIN + bq * 16;
    const __nv_bfloat16* wl = g_Wtlo + (size_t)(c0 + br) * FIN + bq * 16;
    uint32_t aDst[4], bDst[2];
#pragma unroll
    for (int q = 0; q < 4; q++) aDst[q] = SWZ((uint32_t)(ar * 128 + ah_ * 64 + q * 16));
#pragma unroll
    for (int q = 0; q < 2; q++) bDst[q] = SWZ((uint32_t)(br * 128 + bq * 32 + q * 16));

    const int wr = wid & 3, wc = wid >> 2;
    uint32_t aOff[4], bOff[2][4];
    {
        uint32_t aBase = (uint32_t)((wr * 32 + (l & 15)) * 128 + ((l >> 4) << 4));
#pragma unroll
        for (int ks = 0; ks < 4; ks++) aOff[ks] = SWZ(aBase + ks * 32);
#pragma unroll
        for (int gg = 0; gg < 2; gg++) {
            uint32_t bBase = (uint32_t)((wc * 32 + gg * 16 + (l & 15)) * 128 + ((l >> 4) << 4));
#pragma unroll
            for (int ks = 0; ks < 4; ks++) bOff[gg][ks] = SWZ(bBase + ks * 32);
        }
    }

    float acc[2][4][4];
#pragma unroll
    for (int mt = 0; mt < 2; mt++)
#pragma unroll
        for (int nt = 0; nt < 4; nt++)
#pragma unroll
            for (int q = 0; q < 4; q++) acc[mt][nt][q] = 0.f;

    auto stage = [&](int chunk) {
        const int k0 = chunk * 64;
        const int buf = chunk & 1;
        const uint32_t pah = sb + GA_H(buf), pal = sb + GA_L(buf);
        const uint32_t pbh = sb + GB_H(buf), pbl = sb + GB_L(buf);
#pragma unroll
        for (int q = 0; q < 4; q++) CP_ASYNC16(pah + aDst[q], xh + k0 + q * 8);
#pragma unroll
        for (int q = 0; q < 4; q++) CP_ASYNC16(pal + aDst[q], xl + k0 + q * 8);
#pragma unroll
        for (int q = 0; q < 2; q++) CP_ASYNC16(pbh + bDst[q], wh + k0 + q * 8);
#pragma unroll
        for (int q = 0; q < 2; q++) CP_ASYNC16(pbl + bDst[q], wl + k0 + q * 8);
    };

    auto compute = [&](int buf) {
        const uint32_t tAh = sb + GA_H(buf), tAl = sb + GA_L(buf);
        const uint32_t tBh = sb + GB_H(buf), tBl = sb + GB_L(buf);
#pragma unroll
        for (int ks = 0; ks < 4; ks++) {
            uint32_t ah0[4], ah1[4], al0[4], al1[4];
            ldsm4(ah0, tAh + aOff[ks]);
            ldsm4(ah1, tAh + aOff[ks] + 2048);
            ldsm4(al0, tAl + aOff[ks]);
            ldsm4(al1, tAl + aOff[ks] + 2048);
#pragma unroll
            for (int gg = 0; gg < 2; gg++) {
                uint32_t bh[4], bl[4];
                ldsm4(bh, tBh + bOff[gg][ks]);
                ldsm4(bl, tBl + bOff[gg][ks]);
#pragma unroll
                for (int j = 0; j < 2; j++) {
                    int nt = gg * 2 + j;
                    mma_bf16(acc[0][nt], ah0, bh[j], bh[j + 2]);
                    mma_bf16(acc[0][nt], al0, bh[j], bh[j + 2]);
                    mma_bf16(acc[0][nt], ah0, bl[j], bl[j + 2]);
                    mma_bf16(acc[1][nt], ah1, bh[j], bh[j + 2]);
                    mma_bf16(acc[1][nt], al1, bh[j], bh[j + 2]);
                    mma_bf16(acc[1][nt], ah1, bl[j], bl[j + 2]);
                }
            }
        }
    };

    stage(0);
    CP_COMMIT();
    CP_WAIT0();
    __syncthreads();
    for (int chunk = 0; chunk < 8; chunk++) {
        if (chunk + 1 < 8) { stage(chunk + 1); CP_COMMIT(); }
        compute(chunk & 1);
        CP_WAIT0();
        __syncthreads();
    }

    // ==== fused epilogue ====
    const int rq = l >> 2, cq = (l & 3) * 2;

    float ps[2][2] = {{0.f, 0.f}, {0.f, 0.f}};
    float pd[2][2] = {{0.f, 0.f}, {0.f, 0.f}};
#pragma unroll
    for (int nt = 0; nt < 4; nt++) {
        int cg = c0 + wc * 32 + nt * 8 + cq;
        int o = cg & 127;
        float2 bias = *(const float2*)&b[cg];
        float as0 = aw[h * 256 + o], as1 = aw[h * 256 + o + 1];
        float ad0 = aw[h * 256 + 128 + o], ad1 = aw[h * 256 + 128 + o + 1];
#pragma unroll
        for (int mt = 0; mt < 2; mt++) {
            acc[mt][nt][0] += bias.x; acc[mt][nt][1] += bias.y;
            acc[mt][nt][2] += bias.x; acc[mt][nt][3] += bias.y;
            ps[mt][0] = fmaf(acc[mt][nt][0], as0, fmaf(acc[mt][nt][1], as1, ps[mt][0]));
            ps[mt][1] = fmaf(acc[mt][nt][2], as0, fmaf(acc[mt][nt][3], as1, ps[mt][1]));
            pd[mt][0] = fmaf(acc[mt][nt][0], ad0, fmaf(acc[mt][nt][1], ad1, pd[mt][0]));
            pd[mt][1] = fmaf(acc[mt][nt][2], ad0, fmaf(acc[mt][nt][3], ad1, pd[mt][1]));
        }
    }
#pragma unroll
    for (int off = 1; off <= 2; off <<= 1) {
#pragma unroll
        for (int mt = 0; mt < 2; mt++) {
            ps[mt][0] += __shfl_xor_sync(0xffffffffu, ps[mt][0], off);
            ps[mt][1] += __shfl_xor_sync(0xffffffffu, ps[mt][1], off);
            pd[mt][0] += __shfl_xor_sync(0xffffffffu, pd[mt][0], off);
            pd[mt][1] += __shfl_xor_sync(0xffffffffu, pd[mt][1], off);
        }
    }
    if ((l & 3) == 0) {
#pragma unroll
        for (int mt = 0; mt < 2; mt++) {
            int n = m0 + wr * 32 + mt * 16 + rq;
            atomicAdd(&g_src[h * NN + n], ps[mt][0]);
            atomicAdd(&g_src[h * NN + n + 8], ps[mt][1]);
            atomicAdd(&g_dst[h * NN + n], pd[mt][0]);
            atomicAdd(&g_dst[h * NN + n + 8], pd[mt][1]);
        }
    }

    // transpose via smem + fp16 cvt + coalesced STG
    __syncthreads();
    float* tf = (float*)smem;
#pragma unroll
    for (int nt = 0; nt < 4; nt++) {
        int c = wc * 32 + nt * 8 + cq;
#pragma unroll
        for (int mt = 0; mt < 2; mt++) {
            int m = wr * 32 + mt * 16 + rq;
            tf[c * 132 + m] = acc[mt][nt][0];
            tf[(c + 1) * 132 + m] = acc[mt][nt][1];
            tf[c * 132 + m + 8] = acc[mt][nt][2];
            tf[(c + 1) * 132 + m + 8] = acc[mt][nt][3];
        }
    }
    __syncthreads();
    {
        const int c = t >> 2, seg = t & 3;
        const float* src = tf + c * 132 + seg * 32;
        __align__(16) __half hb[32];
#pragma unroll
        for (int k = 0; k < 32; k++) hb[k] = __float2half_rn(src[k]);
        __half* dhi = g_Ht + (size_t)(c0 + c) * NN + m0 + seg * 32;
#pragma unroll
        for (int q = 0; q < 4; q++)
            *(uint4*)(dhi + q * 8) = *(const uint4*)(hb + q * 8);
    }
}

// ---------------- Kernel 4: out = softmax(P) @ H, fp16 single-term, 64-wide chunks ----------------
// smem: A[2]@0 (8KB ea), B[2]@16K (16KB ea), srow@48K ; 48.5KB -> 3 CTA/SM target
#define SM_A(buf) ((buf) * 8192)
#define SM_B(buf) (16384 + (buf) * 16384)
#define SM_SROW 49152
#define SMEM_TOTAL (49152 + 512)

__global__ __launch_bounds__(256, 3) void k_attn_mma(const int* __restrict__ adj, float* __restrict__ out)
{
    extern __shared__ char smem[];
    const uint32_t sb = smem_u32(smem);
    const int t = threadIdx.x;
    const int wid = t >> 5, l = t & 31;
    const int h = blockIdx.x & 3;
    const int n0 = (blockIdx.x >> 2) * 64;

    // ---- staging roles ----
    const int np = t >> 2, mg = (t & 3) * 16;     // P: row np (0..63), 16 m's
    const int cr = t >> 1, mh = (t & 1) * 32;     // H: row cr (0..127), 32 m's
    const float sS = g_src[h * NN + n0 + np];
    const int* arow = adj + (size_t)(n0 + np) * NN + mg;
    const float* gdst = g_dst + h * NN + mg;
    const __half* ght = g_Ht + (size_t)(h * 128 + cr) * NN + mh;
    uint32_t hDst[4], pDst[2];
#pragma unroll
    for (int q = 0; q < 4; q++) hDst[q] = SWZ((uint32_t)(cr * 128 + mh * 2 + q * 16));
#pragma unroll
    for (int q = 0; q < 2; q++) pDst[q] = SWZ((uint32_t)(np * 128 + mg * 2 + q * 16));

    // ---- compute role: warp (wr 0..3, wc 0..1) owns 16n x 64c ----
    const int wr = wid & 3;
    const int wc = wid >> 2;
    uint32_t aOff[4], bOff0[4];
    {
        uint32_t aBase = (uint32_t)((wr * 16 + (l & 15)) * 128 + ((l >> 4) << 4));
        uint32_t bBase = (uint32_t)((wc * 64 + (l & 15)) * 128 + ((l >> 4) << 4));
#pragma unroll
        for (int ks = 0; ks < 4; ks++) {
            aOff[ks] = SWZ(aBase + ks * 32);
            bOff0[ks] = SWZ(bBase + ks * 32);
        }
    }

    float acc[8][4];
#pragma unroll
    for (int nt = 0; nt < 8; nt++)
#pragma unroll
        for (int q = 0; q < 4; q++) acc[nt][q] = 0.f;

    float psum = 0.f;

    auto stageH = [&](int chunk) {
        const int m0 = chunk * 64;
        const uint32_t bB = sb + SM_B(chunk & 1);
#pragma unroll
        for (int q = 0; q < 4; q++) CP_ASYNC16(bB + hDst[q], ght + m0 + q * 8);
    };

    auto stageP = [&](int chunk) {
        const int m0 = chunk * 64;
        char* Ah = smem + SM_A(chunk & 1);
#pragma unroll
        for (int half = 0; half < 2; half++) {
            const int mo = m0 + half * 8;
            int4 a0 = *(const int4*)(arow + mo);
            int4 a1 = *(const int4*)(arow + mo + 4);
            float4 d0 = *(const float4*)(gdst + mo);
            float4 d1 = *(const float4*)(gdst + mo + 4);
            int av[8] = {a0.x, a0.y, a0.z, a0.w, a1.x, a1.y, a1.z, a1.w};
            float dv[8] = {d0.x, d0.y, d0.z, d0.w, d1.x, d1.y, d1.z, d1.w};
            __align__(16) __half hb[8];
#pragma unroll
            for (int j = 0; j < 8; j++) {
                float xx = sS + dv[j];
                float e = xx > 0.f ? xx : ALPHA * xx;
                float p = (av[j] > 0) ? __expf(e) * PSCALE : 0.f;
                __half ph = __float2half_rn(p);
                hb[j] = ph;
                psum += __half2float(ph);
            }
            *(uint4*)(Ah + pDst[half]) = *(const uint4*)hb;
        }
    };

    auto compute = [&](int buf) {
        const uint32_t tA = sb + SM_A(buf);
        const uint32_t tB = sb + SM_B(buf);
#pragma unroll
        for (int ks = 0; ks < 4; ks++) {
            uint32_t ap[4];
            ldsm4(ap, tA + aOff[ks]);
#pragma unroll
            for (int gg = 0; gg < 4; gg++) {
                uint32_t bh[4];
                ldsm4(bh, tB + bOff0[ks] + gg * 2048);
#pragma unroll
                for (int j = 0; j < 2; j++)
                    mma_f16(acc[gg * 2 + j], ap, bh[j], bh[j + 2]);
            }
        }
    };

    // prologue
    stageH(0);
    CP_COMMIT();
    stageP(0);
    CP_WAIT0();
    __syncthreads();

    for (int chunk = 0; chunk < 64; chunk++) {
        if (chunk + 1 < 64) {
            stageH(chunk + 1);
            CP_COMMIT();
            stageP(chunk + 1);
        }
        compute(chunk & 1);
        CP_WAIT0();
        __syncthreads();
    }

    // ---- row-sum reduction: 4 threads per row ----
    psum += __shfl_xor_sync(0xffffffffu, psum, 1);
    psum += __shfl_xor_sync(0xffffffffu, psum, 2);
    float* srow = (float*)(smem + SM_SROW);
    if ((t & 3) == 0) srow[np] = psum;
    __syncthreads();

    // ---- epilogue: normalize + store (scale cancels exactly) ----
    const int rq = l >> 2, cq = (l & 3) * 2;
    const float inv0 = 1.0f / srow[wr * 16 + rq];
    const float inv1 = 1.0f / srow[wr * 16 + rq + 8];
#pragma unroll
    for (int nt = 0; nt < 8; nt++) {
        int n = n0 + wr * 16 + rq;
        int cg = h * FOUT + wc * 64 + nt * 8 + cq;
        float2 v0 = {acc[nt][0] * inv0, acc[nt][1] * inv0};
        float2 v1 = {acc[nt][2] * inv1, acc[nt][3] * inv1};
        *(float2*)&out[(size_t)n * COUT + cg] = v0;
        *(float2*)&out[(size_t)(n + 8) * COUT + cg] = v1;
    }
}

// ---------------- launch ----------------
extern "C" void kernel_launch(void* const* d_in, const int* in_sizes, int n_in,
                              void* d_out, int out_size)
{
    const float* x   = (const float*)d_in[0];
    const int*   adj = (const int*)d_in[1];
    const float* W   = (const float*)d_in[2];
    const float* b   = (const float*)d_in[3];
    const float* aw  = (const float*)d_in[4];
    const float* ab  = (const float*)d_in[5];
    float* out = (float*)d_out;

    (void)cudaFuncSetAttribute(k_gemm_h, cudaFuncAttributeMaxDynamicSharedMemorySize, GSMEM);
    (void)cudaFuncSetAttribute(k_attn_mma, cudaFuncAttributeMaxDynamicSharedMemorySize, SMEM_TOTAL);

    k_init<<<HEADS * NN / 256, 256>>>(ab);
    k_split_x<<<NN * FIN / (256 * 8), 256>>>(x);
    k_split_w<<<dim3(FIN / 32, FOUT / 32, HEADS), 256>>>(W);
    k_gemm_h<<<dim3(NN / 128, COUT / 64), 256, GSMEM>>>(b, aw);
    k_attn_mma<<<256, 256, SMEM_TOTAL>>>(adj, out);
}

// round 15
// speedup vs baseline: 1.2285x; 1.0169x over previous
#include <cuda_runtime.h>
#include <cuda_bf16.h>
#include <cuda_fp16.h>
#include <stdint.h>

#define NN 4096
#define FIN 512
#define FOUT 128
#define HEADS 4
#define COUT 512
#define ALPHA 0.2f
#define PSCALE 0.015625f   // 2^-6, cancels in normalization

// ---------------- scratch ----------------
__device__ __align__(128) float g_src[HEADS * NN];
__device__ __align__(128) float g_dst[HEADS * NN];
__device__ __align__(128) __half g_Ht[COUT * NN];               // [c][m] fp16
__device__ __align__(128) __nv_bfloat16 g_xhi[NN * FIN];        // [m][i]
__device__ __align__(128) __nv_bfloat16 g_xlo[NN * FIN];
__device__ __align__(128) __nv_bfloat16 g_Wthi[COUT * FIN];     // [c][i]
__device__ __align__(128) __nv_bfloat16 g_Wtlo[COUT * FIN];

// ---------------- helpers ----------------
__device__ __forceinline__ uint32_t smem_u32(const void* p) {
    uint32_t a;
    asm("{ .reg .u64 t; cvta.to.shared.u64 t, %1; cvt.u32.u64 %0, t; }" : "=r"(a) : "l"(p));
    return a;
}
#define SWZ(off) ((off) ^ (((off) >> 3) & 0x70))   // 128B rows
#define CP_ASYNC16(dst, src) \
    asm volatile("cp.async.cg.shared.global [%0], [%1], 16;" :: "r"(dst), "l"(src) : "memory")
#define CP_COMMIT() asm volatile("cp.async.commit_group;" ::: "memory")
#define CP_WAIT0()  asm volatile("cp.async.wait_group 0;" ::: "memory")

__device__ __forceinline__ void ldsm4(uint32_t* r, uint32_t a) {
    asm volatile("ldmatrix.sync.aligned.m8n8.x4.shared.b16 {%0,%1,%2,%3}, [%4];"
                 : "=r"(r[0]), "=r"(r[1]), "=r"(r[2]), "=r"(r[3]) : "r"(a));
}
__device__ __forceinline__ void mma_bf16(float* d, const uint32_t* a, uint32_t b0, uint32_t b1) {
    asm volatile(
        "mma.sync.aligned.m16n8k16.row.col.f32.bf16.bf16.f32 "
        "{%0,%1,%2,%3},{%4,%5,%6,%7},{%8,%9},{%0,%1,%2,%3};"
        : "+f"(d[0]), "+f"(d[1]), "+f"(d[2]), "+f"(d[3])
        : "r"(a[0]), "r"(a[1]), "r"(a[2]), "r"(a[3]), "r"(b0), "r"(b1));
}
__device__ __forceinline__ void mma_f16(float* d, const uint32_t* a, uint32_t b0, uint32_t b1) {
    asm volatile(
        "mma.sync.aligned.m16n8k16.row.col.f32.f16.f16.f32 "
        "{%0,%1,%2,%3},{%4,%5,%6,%7},{%8,%9},{%0,%1,%2,%3};"
        : "+f"(d[0]), "+f"(d[1]), "+f"(d[2]), "+f"(d[3])
        : "r"(a[0]), "r"(a[1]), "r"(a[2]), "r"(a[3]), "r"(b0), "r"(b1));
}
__device__ __forceinline__ void split_bf16(float v, __nv_bfloat16& hi, __nv_bfloat16& lo) {
    hi = __float2bfloat16(v);
    lo = __float2bfloat16(v - __bfloat162float(hi));
}

// ---------------- Kernel I: init scores ----------------
__global__ __launch_bounds__(256) void k_init(const float* __restrict__ ab)
{
    const int idx = blockIdx.x * 256 + threadIdx.x;
    g_src[idx] = ab[idx >> 12];
    g_dst[idx] = 0.f;
}

// ---------------- Kernel A: split x into bf16 hi/lo ----------------
__global__ __launch_bounds__(256) void k_split_x(const float* __restrict__ x)
{
    const int base = (blockIdx.x * 256 + threadIdx.x) * 8;
    float4 v0 = *(const float4*)(x + base);
    float4 v1 = *(const float4*)(x + base + 4);
    float v[8] = {v0.x, v0.y, v0.z, v0.w, v1.x, v1.y, v1.z, v1.w};
    __align__(16) __nv_bfloat16 hb[8], lb[8];
#pragma unroll
    for (int j = 0; j < 8; j++) split_bf16(v[j], hb[j], lb[j]);
    *(uint4*)(g_xhi + base) = *(const uint4*)hb;
    *(uint4*)(g_xlo + base) = *(const uint4*)lb;
}

// ---------------- Kernel B: W[h][i][o] -> Wt[c][i] bf16 hi/lo ----------------
__global__ __launch_bounds__(256) void k_split_w(const float* __restrict__ W)
{
    __shared__ float tile[32][33];
    const int tx = threadIdx.x & 31, ty = threadIdx.x >> 5;
    const int i0 = blockIdx.x * 32, o0 = blockIdx.y * 32, h = blockIdx.z;
#pragma unroll
    for (int k = 0; k < 4; k++)
        tile[ty + 8 * k][tx] = W[((size_t)h * FIN + i0 + ty + 8 * k) * FOUT + o0 + tx];
    __syncthreads();
#pragma unroll
    for (int k = 0; k < 4; k++) {
        int o = o0 + ty + 8 * k;
        float v = tile[tx][ty + 8 * k];
        __nv_bfloat16 hi, lo;
        split_bf16(v, hi, lo);
        g_Wthi[(size_t)(h * FOUT + o) * FIN + i0 + tx] = hi;
        g_Wtlo[(size_t)(h * FOUT + o) * FIN + i0 + tx] = lo;
    }
}

// ---------------- Kernel 1: h = x @ Wc + b via HMMA (bf16 3-term) ----------------
// Fused epilogue: score partials (atomicAdd) + transpose + fp16 cvt of h.
#define GA_H(buf) ((buf) * 16384)
#define GA_L(buf) (32768 + (buf) * 16384)
#define GB_H(buf) (65536 + (buf) * 8192)
#define GB_L(buf) (81920 + (buf) * 8192)
#define GSMEM 98304

__global__ __launch_bounds__(256, 2) void k_gemm_h(
    const float* __restrict__ b, const float* __restrict__ aw)
{
    extern __shared__ char smem[];
    const uint32_t sb = smem_u32(smem);
    const int t = threadIdx.x;
    const int wid = t >> 5, l = t & 31;
    const int m0 = blockIdx.x * 128;
    const int c0 = blockIdx.y * 64;
    const int h = c0 >> 7;

    const int ar = t >> 1, ah_ = (t & 1);
    const int br = t >> 2, bq = (t & 3);
    const __nv_bfloat16* xh = g_xhi + (size_t)(m0 + ar) * FIN + ah_ * 32;
    const __nv_bfloat16* xl = g_xlo + (size_t)(m0 + ar) * FIN + ah_ * 32;
    const __nv_bfloat16* wh = g_Wthi + (size_t)(c0 + br) * FIN + bq * 16;
    const __nv_bfloat16* wl = g_Wtlo + (size_t)(c0 + br) * FIN + bq * 16;
    uint32_t aDst[4], bDst[2];
#pragma unroll
    for (int q = 0; q < 4; q++) aDst[q] = SWZ((uint32_t)(ar * 128 + ah_ * 64 + q * 16));
#pragma unroll
    for (int q = 0; q < 2; q++) bDst[q] = SWZ((uint32_t)(br * 128 + bq * 32 + q * 16));

    const int wr = wid & 3, wc = wid >> 2;
    uint32_t aOff[4], bOff[2][4];
    {
        uint32_t aBase = (uint32_t)((wr * 32 + (l & 15)) * 128 + ((l >> 4) << 4));
#pragma unroll
        for (int ks = 0; ks < 4; ks++) aOff[ks] = SWZ(aBase + ks * 32);
#pragma unroll
        for (int gg = 0; gg < 2; gg++) {
            uint32_t bBase = (uint32_t)((wc * 32 + gg * 16 + (l & 15)) * 128 + ((l >> 4) << 4));
#pragma unroll
            for (int ks = 0; ks < 4; ks++) bOff[gg][ks] = SWZ(bBase + ks * 32);
        }
    }

    float acc[2][4][4];
#pragma unroll
    for (int mt = 0; mt < 2; mt++)
#pragma unroll
        for (int nt = 0; nt < 4; nt++)
#pragma unroll
            for (int q = 0; q < 4; q++) acc[mt][nt][q] = 0.f;

    auto stage = [&](int chunk) {
        const int k0 = chunk * 64;
        const int buf = chunk & 1;
        const uint32_t pah = sb + GA_H(buf), pal = sb + GA_L(buf);
        const uint32_t pbh = sb + GB_H(buf), pbl = sb + GB_L(buf);
#pragma unroll
        for (int q = 0; q < 4; q++) CP_ASYNC16(pah + aDst[q], xh + k0 + q * 8);
#pragma unroll
        for (int q = 0; q < 4; q++) CP_ASYNC16(pal + aDst[q], xl + k0 + q * 8);
#pragma unroll
        for (int q = 0; q < 2; q++) CP_ASYNC16(pbh + bDst[q], wh + k0 + q * 8);
#pragma unroll
        for (int q = 0; q < 2; q++) CP_ASYNC16(pbl + bDst[q], wl + k0 + q * 8);
    };

    auto compute = [&](int buf) {
        const uint32_t tAh = sb + GA_H(buf), tAl = sb + GA_L(buf);
        const uint32_t tBh = sb + GB_H(buf), tBl = sb + GB_L(buf);
#pragma unroll
        for (int ks = 0; ks < 4; ks++) {
            uint32_t ah0[4], ah1[4], al0[4], al1[4];
            ldsm4(ah0, tAh + aOff[ks]);
            ldsm4(ah1, tAh + aOff[ks] + 2048);
            ldsm4(al0, tAl + aOff[ks]);
            ldsm4(al1, tAl + aOff[ks] + 2048);
#pragma unroll
            for (int gg = 0; gg < 2; gg++) {
                uint32_t bh[4], bl[4];
                ldsm4(bh, tBh + bOff[gg][ks]);
                ldsm4(bl, tBl + bOff[gg][ks]);
#pragma unroll
                for (int j = 0; j < 2; j++) {
                    int nt = gg * 2 + j;
                    mma_bf16(acc[0][nt], ah0, bh[j], bh[j + 2]);
                    mma_bf16(acc[0][nt], al0, bh[j], bh[j + 2]);
                    mma_bf16(acc[0][nt], ah0, bl[j], bl[j + 2]);
                    mma_bf16(acc[1][nt], ah1, bh[j], bh[j + 2]);
                    mma_bf16(acc[1][nt], al1, bh[j], bh[j + 2]);
                    mma_bf16(acc[1][nt], ah1, bl[j], bl[j + 2]);
                }
            }
        }
    };

    stage(0);
    CP_COMMIT();
    CP_WAIT0();
    __syncthreads();
    for (int chunk = 0; chunk < 8; chunk++) {
        if (chunk + 1 < 8) { stage(chunk + 1); CP_COMMIT(); }
        compute(chunk & 1);
        CP_WAIT0();
        __syncthreads();
    }

    // ==== fused epilogue ====
    const int rq = l >> 2, cq = (l & 3) * 2;

    float ps[2][2] = {{0.f, 0.f}, {0.f, 0.f}};
    float pd[2][2] = {{0.f, 0.f}, {0.f, 0.f}};
#pragma unroll
    for (int nt = 0; nt < 4; nt++) {
        int cg = c0 + wc * 32 + nt * 8 + cq;
        int o = cg & 127;
        float2 bias = *(const float2*)&b[cg];
        float as0 = aw[h * 256 + o], as1 = aw[h * 256 + o + 1];
        float ad0 = aw[h * 256 + 128 + o], ad1 = aw[h * 256 + 128 + o + 1];
#pragma unroll
        for (int mt = 0; mt < 2; mt++) {
            acc[mt][nt][0] += bias.x; acc[mt][nt][1] += bias.y;
            acc[mt][nt][2] += bias.x; acc[mt][nt][3] += bias.y;
            ps[mt][0] = fmaf(acc[mt][nt][0], as0, fmaf(acc[mt][nt][1], as1, ps[mt][0]));
            ps[mt][1] = fmaf(acc[mt][nt][2], as0, fmaf(acc[mt][nt][3], as1, ps[mt][1]));
            pd[mt][0] = fmaf(acc[mt][nt][0], ad0, fmaf(acc[mt][nt][1], ad1, pd[mt][0]));
            pd[mt][1] = fmaf(acc[mt][nt][2], ad0, fmaf(acc[mt][nt][3], ad1, pd[mt][1]));
        }
    }
#pragma unroll
    for (int off = 1; off <= 2; off <<= 1) {
#pragma unroll
        for (int mt = 0; mt < 2; mt++) {
            ps[mt][0] += __shfl_xor_sync(0xffffffffu, ps[mt][0], off);
            ps[mt][1] += __shfl_xor_sync(0xffffffffu, ps[mt][1], off);
            pd[mt][0] += __shfl_xor_sync(0xffffffffu, pd[mt][0], off);
            pd[mt][1] += __shfl_xor_sync(0xffffffffu, pd[mt][1], off);
        }
    }
    if ((l & 3) == 0) {
#pragma unroll
        for (int mt = 0; mt < 2; mt++) {
            int n = m0 + wr * 32 + mt * 16 + rq;
            atomicAdd(&g_src[h * NN + n], ps[mt][0]);
            atomicAdd(&g_src[h * NN + n + 8], ps[mt][1]);
            atomicAdd(&g_dst[h * NN + n], pd[mt][0]);
            atomicAdd(&g_dst[h * NN + n + 8], pd[mt][1]);
        }
    }

    // transpose via smem + fp16 cvt + coalesced STG
    __syncthreads();
    float* tf = (float*)smem;
#pragma unroll
    for (int nt = 0; nt < 4; nt++) {
        int c = wc * 32 + nt * 8 + cq;
#pragma unroll
        for (int mt = 0; mt < 2; mt++) {
            int m = wr * 32 + mt * 16 + rq;
            tf[c * 132 + m] = acc[mt][nt][0];
            tf[(c + 1) * 132 + m] = acc[mt][nt][1];
            tf[c * 132 + m + 8] = acc[mt][nt][2];
            tf[(c + 1) * 132 + m + 8] = acc[mt][nt][3];
        }
    }
    __syncthreads();
    {
        const int c = t >> 2, seg = t & 3;
        const float* src = tf + c * 132 + seg * 32;
        __align__(16) __half hb[32];
#pragma unroll
        for (int k = 0; k < 32; k++) hb[k] = __float2half_rn(src[k]);
        __half* dhi = g_Ht + (size_t)(c0 + c) * NN + m0 + seg * 32;
#pragma unroll
        for (int q = 0; q < 4; q++)
            *(uint4*)(dhi + q * 8) = *(const uint4*)(hb + q * 8);
    }
}

// ---------------- Kernel 4: out = softmax(P) @ H, fp16, 64-wide chunks, sdst in smem ----------------
// smem: A[2]@0 (8KB ea), B[2]@16K (16KB ea), sdst@48K (16KB), srow@64K ; 64.5KB -> 3 CTA/SM
#define SM_A(buf) ((buf) * 8192)
#define SM_B(buf) (16384 + (buf) * 16384)
#define SM_SDST 49152
#define SM_SROW 65536
#define SMEM_TOTAL (65536 + 512)

__global__ __launch_bounds__(256, 3) void k_attn_mma(const int* __restrict__ adj, float* __restrict__ out)
{
    extern __shared__ char smem[];
    const uint32_t sb = smem_u32(smem);
    const int t = threadIdx.x;
    const int wid = t >> 5, l = t & 31;
    const int h = blockIdx.x & 3;
    const int n0 = (blockIdx.x >> 2) * 64;

    // ---- stage s_dst row for this head into smem (16KB, once) ----
    {
        float4* sd = (float4*)(smem + SM_SDST);
        const float4* gs = (const float4*)(g_dst + h * NN);
#pragma unroll
        for (int r = 0; r < 4; r++) sd[t + 256 * r] = gs[t + 256 * r];
    }

    // ---- staging roles ----
    const int np = t >> 2, mg = (t & 3) * 16;     // P: row np (0..63), 16 m's
    const int cr = t >> 1, mh = (t & 1) * 32;     // H: row cr (0..127), 32 m's
    const float sS = g_src[h * NN + n0 + np];
    const int* arow = adj + (size_t)(n0 + np) * NN + mg;
    const float* sdst = (const float*)(smem + SM_SDST) + mg;
    const __half* ght = g_Ht + (size_t)(h * 128 + cr) * NN + mh;
    uint32_t hDst[4], pDst[2];
#pragma unroll
    for (int q = 0; q < 4; q++) hDst[q] = SWZ((uint32_t)(cr * 128 + mh * 2 + q * 16));
#pragma unroll
    for (int q = 0; q < 2; q++) pDst[q] = SWZ((uint32_t)(np * 128 + mg * 2 + q * 16));

    // ---- compute role: warp (wr 0..3, wc 0..1) owns 16n x 64c ----
    const int wr = wid & 3;
    const int wc = wid >> 2;
    uint32_t aOff[4], bOff0[4];
    {
        uint32_t aBase = (uint32_t)((wr * 16 + (l & 15)) * 128 + ((l >> 4) << 4));
        uint32_t bBase = (uint32_t)((wc * 64 + (l & 15)) * 128 + ((l >> 4) << 4));
#pragma unroll
        for (int ks = 0; ks < 4; ks++) {
            aOff[ks] = SWZ(aBase + ks * 32);
            bOff0[ks] = SWZ(bBase + ks * 32);
        }
    }

    float acc[8][4];
#pragma unroll
    for (int nt = 0; nt < 8; nt++)
#pragma unroll
        for (int q = 0; q < 4; q++) acc[nt][q] = 0.f;

    float psum = 0.f;

    auto stageH = [&](int chunk) {
        const int m0 = chunk * 64;
        const uint32_t bB = sb + SM_B(chunk & 1);
#pragma unroll
        for (int q = 0; q < 4; q++) CP_ASYNC16(bB + hDst[q], ght + m0 + q * 8);
    };

    auto stageP = [&](int chunk) {
        const int m0 = chunk * 64;
        char* Ah = smem + SM_A(chunk & 1);
#pragma unroll
        for (int half = 0; half < 2; half++) {
            const int mo = m0 + half * 8;
            int4 a0 = *(const int4*)(arow + mo);
            int4 a1 = *(const int4*)(arow + mo + 4);
            float4 d0 = *(const float4*)(sdst + mo);
            float4 d1 = *(const float4*)(sdst + mo + 4);
            int av[8] = {a0.x, a0.y, a0.z, a0.w, a1.x, a1.y, a1.z, a1.w};
            float dv[8] = {d0.x, d0.y, d0.z, d0.w, d1.x, d1.y, d1.z, d1.w};
            __align__(16) __half hb[8];
#pragma unroll
            for (int j = 0; j < 8; j++) {
                float xx = sS + dv[j];
                float e = xx > 0.f ? xx : ALPHA * xx;
                float p = (av[j] > 0) ? __expf(e) * PSCALE : 0.f;
                __half ph = __float2half_rn(p);
                hb[j] = ph;
                psum += __half2float(ph);
            }
            *(uint4*)(Ah + pDst[half]) = *(const uint4*)hb;
        }
    };

    auto compute = [&](int buf) {
        const uint32_t tA = sb + SM_A(buf);
        const uint32_t tB = sb + SM_B(buf);
#pragma unroll
        for (int ks = 0; ks < 4; ks++) {
            uint32_t ap[4];
            ldsm4(ap, tA + aOff[ks]);
#pragma unroll
            for (int gg = 0; gg < 4; gg++) {
                uint32_t bh[4];
                ldsm4(bh, tB + bOff0[ks] + gg * 2048);
#pragma unroll
                for (int j = 0; j < 2; j++)
                    mma_f16(acc[gg * 2 + j], ap, bh[j], bh[j + 2]);
            }
        }
    };

    // prologue: sdst must be visible before stageP(0)
    __syncthreads();
    stageH(0);
    CP_COMMIT();
    stageP(0);
    CP_WAIT0();
    __syncthreads();

    for (int chunk = 0; chunk < 64; chunk++) {
        if (chunk + 1 < 64) {
            stageH(chunk + 1);
            CP_COMMIT();
            stageP(chunk + 1);
        }
        compute(chunk & 1);
        CP_WAIT0();
        __syncthreads();
    }

    // ---- row-sum reduction: 4 threads per row ----
    psum += __shfl_xor_sync(0xffffffffu, psum, 1);
    psum += __shfl_xor_sync(0xffffffffu, psum, 2);
    float* srow = (float*)(smem + SM_SROW);
    if ((t & 3) == 0) srow[np] = psum;
    __syncthreads();

    // ---- epilogue: normalize + store (scale cancels exactly) ----
    const int rq = l >> 2, cq = (l & 3) * 2;
    const float inv0 = 1.0f / srow[wr * 16 + rq];
    const float inv1 = 1.0f / srow[wr * 16 + rq + 8];
#pragma unroll
    for (int nt = 0; nt < 8; nt++) {
        int n = n0 + wr * 16 + rq;
        int cg = h * FOUT + wc * 64 + nt * 8 + cq;
        float2 v0 = {acc[nt][0] * inv0, acc[nt][1] * inv0};
        float2 v1 = {acc[nt][2] * inv1, acc[nt][3] * inv1};
        *(float2*)&out[(size_t)n * COUT + cg] = v0;
        *(float2*)&out[(size_t)(n + 8) * COUT + cg] = v1;
    }
}

// ---------------- launch ----------------
extern "C" void kernel_launch(void* const* d_in, const int* in_sizes, int n_in,
                              void* d_out, int out_size)
{
    const float* x   = (const float*)d_in[0];
    const int*   adj = (const int*)d_in[1];
    const float* W   = (const float*)d_in[2];
    const float* b   = (const float*)d_in[3];
    const float* aw  = (const float*)d_in[4];
    const float* ab  = (const float*)d_in[5];
    float* out = (float*)d_out;

    (void)cudaFuncSetAttribute(k_gemm_h, cudaFuncAttributeMaxDynamicSharedMemorySize, GSMEM);
    (void)cudaFuncSetAttribute(k_attn_mma, cudaFuncAttributeMaxDynamicSharedMemorySize, SMEM_TOTAL);

    k_init<<<HEADS * NN / 256, 256>>>(ab);
    k_split_x<<<NN * FIN / (256 * 8), 256>>>(x);
    k_split_w<<<dim3(FIN / 32, FOUT / 32, HEADS), 256>>>(W);
    k_gemm_h<<<dim3(NN / 128, COUT / 64), 256, GSMEM>>>(b, aw);
    k_attn_mma<<<256, 256, SMEM_TOTAL>>>(adj, out);
}